// round 15
// baseline (speedup 1.0000x reference)
#include <cuda_runtime.h>
#include <cuda_fp16.h>
#include <cstdint>

#define NB 64
#define NN 22
#define NF 64
#define NO 64
#define NT 512
#define TT 4              // t-tile width per CTA
#define KF 192            // combined (k,f) contraction dim

typedef unsigned long long u64;

__device__ float d_S[2*NN*NN];     // Chebyshev supports S1, S2 (S0 = I implicit)
__device__ __half d_thT[NO*KF];    // theta^T fp16 [o][kf]
__device__ float4 d_A2q[NB*270];   // per-batch coeff quads [b][row 0..44][cc 0..5]
__device__ float  d_diag[NB*NN];   // per-batch diag att

// ---------------------------------------------------------------------------
__device__ __forceinline__ uint32_t smem_u32(const void* p) {
    uint32_t a;
    asm("{ .reg .u64 t; cvta.to.shared.u64 t, %1; cvt.u32.u64 %0, t; }"
        : "=r"(a) : "l"(p));
    return a;
}
__device__ __forceinline__ void cp_async16(uint32_t dst, const void* src) {
    asm volatile("cp.async.ca.shared.global [%0], [%1], 16;"
                 :: "r"(dst), "l"(src) : "memory");
}
#define CP_COMMIT() asm volatile("cp.async.commit_group;" ::: "memory")
#define CP_WAIT1()  asm volatile("cp.async.wait_group 1;" ::: "memory")
#define CP_WAIT0()  asm volatile("cp.async.wait_group 0;" ::: "memory")

// ---------------------------------------------------------------------------
// warp-mma building blocks
// ---------------------------------------------------------------------------
#define LDSM4T(R, ADDR) \
    asm volatile("ldmatrix.sync.aligned.m8n8.x4.trans.shared.b16 {%0,%1,%2,%3}, [%4];" \
        : "=r"((R)[0]), "=r"((R)[1]), "=r"((R)[2]), "=r"((R)[3]) : "r"(ADDR))

#define LDSM4(R, ADDR) \
    asm volatile("ldmatrix.sync.aligned.m8n8.x4.shared.b16 {%0,%1,%2,%3}, [%4];" \
        : "=r"((R)[0]), "=r"((R)[1]), "=r"((R)[2]), "=r"((R)[3]) : "r"(ADDR))

#define MMA16816(D, A, B0, B1) \
    asm volatile("mma.sync.aligned.m16n8k16.row.col.f32.f16.f16.f32 " \
        "{%0,%1,%2,%3}, {%4,%5,%6,%7}, {%8,%9}, {%0,%1,%2,%3};" \
        : "+f"((D)[0]), "+f"((D)[1]), "+f"((D)[2]), "+f"((D)[3]) \
        : "r"((A)[0]), "r"((A)[1]), "r"((A)[2]), "r"((A)[3]), "r"(B0), "r"(B1))

// SMEM geometry (bytes) -- all dynamic, no static shared arrays
#define A_STRIDE 208      // A[kf][mt]: 96 fp16 = 192 B + 16 pad
#define B_STRIDE 400      // B[o][kf]:  192 fp16 = 384 B + 16 pad
#define A_BYTES  (KF*A_STRIDE)               // 39936
#define OFF_B    A_BYTES                     // 39936
#define RING_OFF (A_BYTES + NO*B_STRIDE)     // 65536: x ring, 4 slots x 2048 B
#define DSMEM_TOTAL (RING_OFF + 4*2048)      // 73728  (x3 = 221184 <= 233472)

// ---------------------------------------------------------------------------
// K_prep: supports + theta^T fp16
// ---------------------------------------------------------------------------
__global__ void k_prep(const float* __restrict__ E, const float* __restrict__ theta) {
    __shared__ float Es[NN*NN];
    __shared__ float P[NN*NN];
    __shared__ float sup[NN*NN];
    int t = threadIdx.x;
    for (int i = t; i < NO*KF; i += 512) {
        int o = i / KF, kf = i % KF;
        d_thT[i] = __float2half(theta[kf*NO + o]);
    }
    if (t < NN*NN) Es[t] = E[t];
    __syncthreads();
    if (t < NN*NN) {
        int i = t / NN, j = t % NN;
        float s = 0.f;
        #pragma unroll
        for (int l = 0; l < NN; l++) s += Es[i*NN + l] * Es[j*NN + l];
        P[t] = fmaxf(s, 0.f);
    }
    __syncthreads();
    if (t < NN) {
        float mx = -1e30f;
        #pragma unroll
        for (int j = 0; j < NN; j++) mx = fmaxf(mx, P[t*NN + j]);
        float den = 0.f;
        #pragma unroll
        for (int j = 0; j < NN; j++) { float e = expf(P[t*NN + j] - mx); sup[t*NN + j] = e; den += e; }
        float inv = 1.f / den;
        #pragma unroll
        for (int j = 0; j < NN; j++) sup[t*NN + j] *= inv;
    }
    __syncthreads();
    if (t < NN*NN) {
        int i = t / NN, j = t % NN;
        float eye = (i == j) ? 1.f : 0.f;
        d_S[t] = sup[t];                       // S1
        float s = 0.f;
        #pragma unroll
        for (int l = 0; l < NN; l++) s += sup[i*NN + l] * sup[l*NN + j];
        d_S[NN*NN + t] = 2.f * s - eye;        // S2
    }
}

// ---------------------------------------------------------------------------
// K_a2: per-batch coefficient quads (rows 0..43 = S-planes; row 44 = zeros)
// ---------------------------------------------------------------------------
__global__ void k_a2(const float* __restrict__ att) {
    int b = blockIdx.x, t = threadIdx.x;
    if (t < 270) {
        int row = t / 6, q = t % 6;
        float c[4] = {0.f, 0.f, 0.f, 0.f};
        if (row < 44) {
            int kk = row / 22, m = row % 22;
            #pragma unroll
            for (int j = 0; j < 4; j++) {
                int n = q*4 + j;
                if (n < NN)
                    c[j] = d_S[kk*NN*NN + n*NN + m] * att[(b*NN + n)*NN + m];
            }
        }
        d_A2q[b*270 + t] = make_float4(c[0], c[1], c[2], c[3]);
    }
    if (t < NN) d_diag[b*NN + t] = att[(b*NN + t)*NN + t];
}

// ---------------------------------------------------------------------------
// Fused main kernel. One CTA per (b, 4-wide t-tile). 384 threads, occ 3.
// Phase 1: n-contraction; coeffs via uniform __ldg float4; x via 4-slot
//          cp.async ring (pair commits, wait_group 1, dual barriers).
// Phase 2: R13-verified 12-warp mma tile + epilogue.
// ---------------------------------------------------------------------------
__global__ void __launch_bounds__(384, 3) k_main(
    const float* __restrict__ x,
    float* __restrict__ out)
{
    extern __shared__ char dsm[];

    const int tid = threadIdx.x;
    const int b   = blockIdx.y;
    const int tt0 = blockIdx.x * TT;
    const uint32_t sbase = smem_u32(dsm);
    const uint32_t ringb = sbase + RING_OFF;
    const float*   xb    = x + (size_t)b*NN*NF*NT + tt0;
    const float*   ringf = (const float*)(dsm + RING_OFF);

    // cp.async: x chunk c = n rows {2c,2c+1}, 2048 B, slot c&3, 128 issuers.
    const int cn2 = tid >> 6;          // 0..1 (valid tid<128)
    const int cf  = tid & 63;
    const float*   csrc0 = xb + ((size_t)cn2*NF + cf)*NT;
    const uint32_t cdst0 = ringb + (uint32_t)((cn2 << 10) | (cf << 4));

    // ---- prologue: group P0 = {B(theta^T), c0, c1}; P1 = {c2, c3} ----
    if (tid < 128) {
        #pragma unroll
        for (int j = 0; j < 12; j++) {
            int i = tid + j*128;
            int o = i / 24, ch = i % 24;
            cp_async16(sbase + OFF_B + o*B_STRIDE + ch*16, d_thT + o*KF + ch*8);
        }
        cp_async16(cdst0,          csrc0);
        cp_async16(cdst0 + 1*2048, csrc0 + 2*NF*NT);   CP_COMMIT();  // P0
        cp_async16(cdst0 + 2*2048, csrc0 + 4*NF*NT);
        cp_async16(cdst0 + 3*2048, csrc0 + 6*NF*NT);   CP_COMMIT();  // P1
    }

    // ---- phase 1: thread = (group, f, t-pair); rows split 15/15/14(+pad) ----
    const int g  = tid >> 7;            // 0..2, warp-uniform
    const int f  = (tid >> 1) & 63;
    const int tp = tid & 1;
    const int r0 = g * 15;
    const float4* a2p = d_A2q + b*270;

    float a0[15], a1[15];
    #pragma unroll
    for (int i = 0; i < 15; i++) { a0[i] = 0.f; a1[i] = 0.f; }

    #pragma unroll
    for (int cc = 0; cc < 5; cc++) {
        if (tid < 128) CP_WAIT1();      // pair cc landed
        __syncthreads();
        // consume pair cc into regs (slots 2cc&3, (2cc+1)&3)
        const float* xpA = ringf + (((2*cc)   & 3) << 9);
        const float* xpB = ringf + (((2*cc+1) & 3) << 9);
        float2 xv0 = *(const float2*)(xpA +       f*4 + tp*2);   // n = 4cc
        float2 xv1 = *(const float2*)(xpA + 256 + f*4 + tp*2);   // n = 4cc+1
        float2 xv2 = *(const float2*)(xpB +       f*4 + tp*2);   // n = 4cc+2
        float2 xv3 = *(const float2*)(xpB + 256 + f*4 + tp*2);   // n = 4cc+3
        __syncthreads();                // slots reusable; prefetch may land
        if (tid < 128 && cc < 4) {
            int cA = 2*cc + 4, cB = 2*cc + 5;
            cp_async16(cdst0 + (uint32_t)((cA & 3) << 11),
                       csrc0 + (size_t)(2*cA)*NF*NT);
            if (cB < 11)
                cp_async16(cdst0 + (uint32_t)((cB & 3) << 11),
                           csrc0 + (size_t)(2*cB)*NF*NT);
            CP_COMMIT();
        }
        #pragma unroll
        for (int i = 0; i < 15; i++) {
            float4 aa = __ldg(&a2p[(r0 + i)*6 + cc]);   // uniform broadcast
            a0[i] = fmaf(aa.x, xv0.x, a0[i]);  a1[i] = fmaf(aa.x, xv0.y, a1[i]);
            a0[i] = fmaf(aa.y, xv1.x, a0[i]);  a1[i] = fmaf(aa.y, xv1.y, a1[i]);
            a0[i] = fmaf(aa.z, xv2.x, a0[i]);  a1[i] = fmaf(aa.z, xv2.y, a1[i]);
            a0[i] = fmaf(aa.w, xv3.x, a0[i]);  a1[i] = fmaf(aa.w, xv3.y, a1[i]);
        }
        if (g == 2) {
            // diag (k=0 plane): A row = f, final at this pair
            #pragma unroll
            for (int j = 0; j < 4; j++) {
                int m = 4*cc + j;
                float2 xv = (j == 0) ? xv0 : (j == 1) ? xv1 : (j == 2) ? xv2 : xv3;
                float dv = __ldg(&d_diag[b*NN + m]);
                __half2 h = __floats2half2_rn(dv*xv.x, dv*xv.y);
                *(uint32_t*)(dsm + f*A_STRIDE + (m*4 + tp*2)*2) = *(uint32_t*)&h;
            }
        }
    }
    // ---- tail: chunk 10 (n = 20, 21), slot 2 ----
    {
        if (tid < 128) CP_WAIT0();
        __syncthreads();
        const float* xpT = ringf + ((10 & 3) << 9);
        float2 xv0 = *(const float2*)(xpT +       f*4 + tp*2);   // n = 20
        float2 xv1 = *(const float2*)(xpT + 256 + f*4 + tp*2);   // n = 21
        #pragma unroll
        for (int i = 0; i < 15; i++) {
            float4 aa = __ldg(&a2p[(r0 + i)*6 + 5]);
            a0[i] = fmaf(aa.x, xv0.x, a0[i]);  a1[i] = fmaf(aa.x, xv0.y, a1[i]);
            a0[i] = fmaf(aa.y, xv1.x, a0[i]);  a1[i] = fmaf(aa.y, xv1.y, a1[i]);
        }
        if (g == 2) {
            #pragma unroll
            for (int j = 0; j < 2; j++) {
                int m = 20 + j;
                float2 xv = (j == 0) ? xv0 : xv1;
                float dv = __ldg(&d_diag[b*NN + m]);
                __half2 h = __floats2half2_rn(dv*xv.x, dv*xv.y);
                *(uint32_t*)(dsm + f*A_STRIDE + (m*4 + tp*2)*2) = *(uint32_t*)&h;
            }
        }
    }
    // ---- store heavy rows: row r -> A[(1 + r/22)*64 + f][m*4 + tp*2] ----
    #pragma unroll
    for (int i = 0; i < 15; i++) {
        int row = r0 + i;
        if (row < 44) {
            int kk = row / 22, m = row - kk*22;
            __half2 h = __floats2half2_rn(a0[i], a1[i]);
            *(uint32_t*)(dsm + ((1 + kk)*64 + f)*A_STRIDE + (m*4 + tp*2)*2)
                = *(uint32_t*)&h;
        }
    }
    __syncthreads();

    // ---- phase 2 (R13-verified): 12 warps = (mt-tile, n-half) ----
    {
        const int w    = tid >> 5;
        const int lane = tid & 31;
        const int mt  = w >> 1;             // 0..5
        const int nh  = w & 1;              // 0..1
        const int m0b = mt * 16;
        const int n0  = nh * 32;

        const int lrow = (lane & 7) + ((lane >> 4) << 3);
        const int lga  = ((lane >> 3) & 1) * 8;
        uint32_t aA = sbase + lrow*A_STRIDE + (m0b + lga)*2;

        const int borow = ((lane >> 4) << 3) + (lane & 7);
        uint32_t aB0 = sbase + OFF_B + (n0 + borow)*B_STRIDE + ((lane >> 3) & 1)*16;
        uint32_t aB1 = aB0 + 16*B_STRIDE;

        float acc[16];
        #pragma unroll
        for (int i = 0; i < 16; i++) acc[i] = 0.f;

        #pragma unroll 4
        for (int s = 0; s < 12; s++) {
            uint32_t ah[4], b0[4], b1[4];
            LDSM4T(ah, aA  + s*(16*A_STRIDE));
            LDSM4 (b0, aB0 + s*32);
            LDSM4 (b1, aB1 + s*32);
            MMA16816(acc +  0, ah, b0[0], b0[1]);
            MMA16816(acc +  4, ah, b0[2], b0[3]);
            MMA16816(acc +  8, ah, b1[0], b1[1]);
            MMA16816(acc + 12, ah, b1[2], b1[3]);
        }

        const int tq   = (lane >> 2) & 3;
        const int mrow = lane >> 4;
        const int q2   = (lane & 3) * 2;
        #pragma unroll
        for (int j = 0; j < 4; j++) {
            #pragma unroll
            for (int i = 0; i < 2; i++) {
                int m = 4*mt + mrow + 2*i;
                if (m < NN) {
                    int o = n0 + j*8 + q2;
                    float* op = out + ((size_t)(b*NN + m)*NO + o)*NT + tt0 + tq;
                    op[0]  = fmaxf(acc[j*4 + i*2 + 0], 0.f);
                    op[NT] = fmaxf(acc[j*4 + i*2 + 1], 0.f);
                }
            }
        }
    }
}

// ---------------------------------------------------------------------------
extern "C" void kernel_launch(void* const* d_in, const int* in_sizes, int n_in,
                              void* d_out, int out_size)
{
    const float* x     = (const float*)d_in[0];   // [B,N,F_in,T]
    const float* att   = (const float*)d_in[1];   // [B,N,N]
    const float* theta = (const float*)d_in[2];   // [K,F_in,F_out]
    const float* emb   = (const float*)d_in[3];   // [N,N]
    float* out = (float*)d_out;                   // [B,N,F_out,T]

    k_prep<<<1, 512>>>(emb, theta);
    k_a2<<<NB, 288>>>(att);

    cudaFuncSetAttribute(k_main, cudaFuncAttributeMaxDynamicSharedMemorySize,
                         DSMEM_TOTAL);
    dim3 grid(NT/TT, NB);
    k_main<<<grid, 384, DSMEM_TOTAL>>>(x, out);
}

// round 16
// speedup vs baseline: 1.4811x; 1.4811x over previous
#include <cuda_runtime.h>
#include <cuda_fp16.h>
#include <cstdint>

#define NB 64
#define NN 22
#define NF 64
#define NO 64
#define NT 512
#define TT 4              // t-tile width per CTA
#define KF 192            // combined (k,f) contraction dim

typedef unsigned long long u64;

__device__ float d_S[2*NN*NN];      // Chebyshev supports S1, S2
__device__ __half d_thT[NO*KF];     // theta^T fp16 [o][kf]
__device__ float d_a2all[NB*1080];  // per batch: 48 rows x 22 coeff + 22 diag + pad

// ---------------------------------------------------------------------------
__device__ __forceinline__ uint32_t smem_u32(const void* p) {
    uint32_t a;
    asm("{ .reg .u64 t; cvta.to.shared.u64 t, %1; cvt.u32.u64 %0, t; }"
        : "=r"(a) : "l"(p));
    return a;
}
__device__ __forceinline__ void cp_async16(uint32_t dst, const void* src) {
    asm volatile("cp.async.ca.shared.global [%0], [%1], 16;"
                 :: "r"(dst), "l"(src) : "memory");
}
#define CP_COMMIT() asm volatile("cp.async.commit_group;" ::: "memory")
#define CP_WAIT1()  asm volatile("cp.async.wait_group 1;" ::: "memory")
#define CP_WAIT0()  asm volatile("cp.async.wait_group 0;" ::: "memory")

// ---------------------------------------------------------------------------
// warp-mma building blocks
// ---------------------------------------------------------------------------
#define LDSM4T(R, ADDR) \
    asm volatile("ldmatrix.sync.aligned.m8n8.x4.trans.shared.b16 {%0,%1,%2,%3}, [%4];" \
        : "=r"((R)[0]), "=r"((R)[1]), "=r"((R)[2]), "=r"((R)[3]) : "r"(ADDR))

#define LDSM4(R, ADDR) \
    asm volatile("ldmatrix.sync.aligned.m8n8.x4.shared.b16 {%0,%1,%2,%3}, [%4];" \
        : "=r"((R)[0]), "=r"((R)[1]), "=r"((R)[2]), "=r"((R)[3]) : "r"(ADDR))

#define MMA16816(D, A, B0, B1) \
    asm volatile("mma.sync.aligned.m16n8k16.row.col.f32.f16.f16.f32 " \
        "{%0,%1,%2,%3}, {%4,%5,%6,%7}, {%8,%9}, {%0,%1,%2,%3};" \
        : "+f"((D)[0]), "+f"((D)[1]), "+f"((D)[2]), "+f"((D)[3]) \
        : "r"((A)[0]), "r"((A)[1]), "r"((A)[2]), "r"((A)[3]), "r"(B0), "r"(B1))

// SMEM geometry (bytes) -- all dynamic
#define A_STRIDE 208      // A[kf][mt]: 96 fp16 = 192 B + 16 pad
#define B_STRIDE 400      // B[o][kf]:  192 fp16 = 384 B + 16 pad
#define OFF_B    39936                        // after A (192*208)
#define OFF_A2   65536                        // after B (64*400)
#define OFF_DIAG (OFF_A2 + 1056*4)            // 69760 (diag floats)
#define RING_OFF (OFF_A2 + 1080*4)            // 69856: ring, 2 slots x 2048 B
#define DSMEM_TOTAL (RING_OFF + 2*2048)       // 73952  (x3 = 221856, fits)

// ---------------------------------------------------------------------------
// K_prep: supports (block 0) + theta^T fp16 (all 8 blocks, strided)
// ---------------------------------------------------------------------------
__global__ void k_prep(const float* __restrict__ E, const float* __restrict__ theta) {
    __shared__ float Es[NN*NN];
    __shared__ float P[NN*NN];
    __shared__ float sup[NN*NN];
    int t = threadIdx.x;
    for (int i = blockIdx.x*512 + t; i < NO*KF; i += 8*512) {
        int o = i / KF, kf = i % KF;
        d_thT[i] = __float2half(theta[kf*NO + o]);
    }
    if (blockIdx.x != 0) return;
    if (t < NN*NN) Es[t] = E[t];
    __syncthreads();
    if (t < NN*NN) {
        int i = t / NN, j = t % NN;
        float s = 0.f;
        #pragma unroll
        for (int l = 0; l < NN; l++) s += Es[i*NN + l] * Es[j*NN + l];
        P[t] = fmaxf(s, 0.f);
    }
    __syncthreads();
    if (t < NN) {
        float mx = -1e30f;
        #pragma unroll
        for (int j = 0; j < NN; j++) mx = fmaxf(mx, P[t*NN + j]);
        float den = 0.f;
        #pragma unroll
        for (int j = 0; j < NN; j++) { float e = expf(P[t*NN + j] - mx); sup[t*NN + j] = e; den += e; }
        float inv = 1.f / den;
        #pragma unroll
        for (int j = 0; j < NN; j++) sup[t*NN + j] *= inv;
    }
    __syncthreads();
    if (t < NN*NN) {
        int i = t / NN, j = t % NN;
        float eye = (i == j) ? 1.f : 0.f;
        d_S[t] = sup[t];                       // S1
        float s = 0.f;
        #pragma unroll
        for (int l = 0; l < NN; l++) s += sup[i*NN + l] * sup[l*NN + j];
        d_S[NN*NN + t] = 2.f * s - eye;        // S2
    }
}

// ---------------------------------------------------------------------------
// K_a2: per-batch coefficients. Layout per batch (1080 floats):
//   [row*22 + n], row 0..43 = S-plane coeffs (row = kk*22+m), rows 44..47 = 0;
//   [1056..1077] = diag att; [1078..1079] pad.
// ---------------------------------------------------------------------------
__global__ void k_a2(const float* __restrict__ att) {
    int b = blockIdx.x;
    for (int t = threadIdx.x; t < 1080; t += 1024) {
        float v = 0.f;
        if (t < 968) {                     // 44 rows x 22 n
            int row = t / 22, n = t % 22;
            int kk = row / 22, m = row % 22;
            v = d_S[kk*NN*NN + n*NN + m] * att[(b*NN + n)*NN + m];
        } else if (t >= 1056 && t < 1078) {
            int m = t - 1056;
            v = att[(b*NN + m)*NN + m];
        }
        d_a2all[b*1080 + t] = v;
    }
}

// ---------------------------------------------------------------------------
// Fused main kernel. One CTA per (b, 4-wide t-tile). 384 threads, occ 3.
// Phase 1: 6 row-groups x 64 f; 8 rows x 4 t in regs; a2 via SMEM broadcast;
//          x via 2-slot cp.async ring (distance-2, regs-consume between bars).
// Phase 2: R13-verified 12-warp mma tile + epilogue.
// ---------------------------------------------------------------------------
__global__ void __launch_bounds__(384, 3) k_main(
    const float* __restrict__ x,
    float* __restrict__ out)
{
    extern __shared__ char dsm[];

    const int tid = threadIdx.x;
    const int b   = blockIdx.y;
    const int tt0 = blockIdx.x * TT;
    const uint32_t sbase = smem_u32(dsm);
    const float*   ringf = (const float*)(dsm + RING_OFF);
    const float*   a2s   = (const float*)(dsm + OFF_A2);
    const float*   diags = (const float*)(dsm + OFF_DIAG);
    const float*   xb    = x + (size_t)b*NN*NF*NT + tt0;

    // ---- prologue: stage B (1536 lines) + a2 (270 lines) via cp.async ----
    #pragma unroll
    for (int j = 0; j < 5; j++) {
        int L = tid + j*384;
        if (L < 1536) {
            int o = L / 24, ch = L % 24;
            cp_async16(sbase + OFF_B + o*B_STRIDE + ch*16, d_thT + o*KF + ch*8);
        } else if (L < 1536 + 270) {
            int q = L - 1536;
            cp_async16(sbase + OFF_A2 + q*16, d_a2all + b*1080 + q*4);
        }
    }
    CP_COMMIT();                                  // group BA (all threads)

    // x ring: chunk c = n rows {2c,2c+1}, 2048 B, slot c&1, 128 issuers
    const int cn2 = tid >> 6;          // 0..1 (valid tid<128)
    const int cf  = tid & 63;
    const float*   csrc0 = xb + ((size_t)cn2*NF + cf)*NT;
    const uint32_t cdst0 = sbase + RING_OFF + (uint32_t)((cn2 << 10) | (cf << 4));
    if (tid < 128) {
        cp_async16(cdst0,        csrc0);            CP_COMMIT();  // c0
        cp_async16(cdst0 + 2048, csrc0 + 2*NF*NT);  CP_COMMIT();  // c1
    }

    // ---- phase 1 ----
    const int G = tid >> 6;            // 0..5, warp-uniform
    const int f = tid & 63;
    const int r0 = G * 8;              // rows r0..r0+7 (44..47 have zero coeff)

    float a[8][4];
    #pragma unroll
    for (int i = 0; i < 8; i++)
        #pragma unroll
        for (int t = 0; t < 4; t++) a[i][t] = 0.f;

    #pragma unroll
    for (int c = 0; c < 11; c++) {
        if (tid < 128) { if (c < 10) CP_WAIT1(); else CP_WAIT0(); }
        else if (c == 0) { CP_WAIT0(); }            // BA group (a2 ready)
        __syncthreads();
        // consume chunk c into regs (slot c&1)
        const float* xp = ringf + ((c & 1) << 9);
        float4 xv0 = *(const float4*)(xp +       f*4);   // n = 2c,   t0..3
        float4 xv1 = *(const float4*)(xp + 256 + f*4);   // n = 2c+1, t0..3
        __syncthreads();                 // slot c&1 reusable
        if (tid < 128 && c < 9) {
            cp_async16(cdst0 + (uint32_t)(((c+2) & 1) << 11),
                       csrc0 + (size_t)(2*(c+2))*NF*NT);
            CP_COMMIT();
        }
        #pragma unroll
        for (int i = 0; i < 8; i++) {
            float2 aa = *(const float2*)(a2s + (r0 + i)*22 + 2*c);  // broadcast
            a[i][0] = fmaf(aa.x, xv0.x, a[i][0]);
            a[i][1] = fmaf(aa.x, xv0.y, a[i][1]);
            a[i][2] = fmaf(aa.x, xv0.z, a[i][2]);
            a[i][3] = fmaf(aa.x, xv0.w, a[i][3]);
            a[i][0] = fmaf(aa.y, xv1.x, a[i][0]);
            a[i][1] = fmaf(aa.y, xv1.y, a[i][1]);
            a[i][2] = fmaf(aa.y, xv1.z, a[i][2]);
            a[i][3] = fmaf(aa.y, xv1.w, a[i][3]);
        }
        if (G == 5) {
            // diag (k=0) plane: A row = f, cols m*4.., final at this chunk
            float d0 = diags[2*c], d1 = diags[2*c + 1];
            __half2 h0 = __floats2half2_rn(d0*xv0.x, d0*xv0.y);
            __half2 h1 = __floats2half2_rn(d0*xv0.z, d0*xv0.w);
            __half2 h2 = __floats2half2_rn(d1*xv1.x, d1*xv1.y);
            __half2 h3 = __floats2half2_rn(d1*xv1.z, d1*xv1.w);
            uint32_t base = sbase + f*A_STRIDE;
            u64 p0 = ((u64)*(uint32_t*)&h1 << 32) | *(uint32_t*)&h0;
            u64 p1 = ((u64)*(uint32_t*)&h3 << 32) | *(uint32_t*)&h2;
            asm volatile("st.shared.b64 [%0], %1;" :: "r"(base + (2*c)*8),   "l"(p0));
            asm volatile("st.shared.b64 [%0], %1;" :: "r"(base + (2*c+1)*8), "l"(p1));
        }
    }
    // ---- store heavy rows: row -> A[(1 + row/22)*64 + f][(row%22)*4] ----
    #pragma unroll
    for (int i = 0; i < 8; i++) {
        int row = r0 + i;
        if (row < 44) {
            int kk = row / 22, m = row - kk*22;
            __half2 h0 = __floats2half2_rn(a[i][0], a[i][1]);
            __half2 h1 = __floats2half2_rn(a[i][2], a[i][3]);
            u64 p = ((u64)*(uint32_t*)&h1 << 32) | *(uint32_t*)&h0;
            asm volatile("st.shared.b64 [%0], %1;"
                :: "r"(sbase + ((1 + kk)*64 + f)*A_STRIDE + m*8), "l"(p));
        }
    }
    __syncthreads();

    // ---- phase 2 (R13-verified): 12 warps = (mt-tile, n-half) ----
    {
        const int w    = tid >> 5;
        const int lane = tid & 31;
        const int mt  = w >> 1;             // 0..5
        const int nh  = w & 1;              // 0..1
        const int m0b = mt * 16;
        const int n0  = nh * 32;

        const int lrow = (lane & 7) + ((lane >> 4) << 3);
        const int lga  = ((lane >> 3) & 1) * 8;
        uint32_t aA = sbase + lrow*A_STRIDE + (m0b + lga)*2;

        const int borow = ((lane >> 4) << 3) + (lane & 7);
        uint32_t aB0 = sbase + OFF_B + (n0 + borow)*B_STRIDE + ((lane >> 3) & 1)*16;
        uint32_t aB1 = aB0 + 16*B_STRIDE;

        float acc[16];
        #pragma unroll
        for (int i = 0; i < 16; i++) acc[i] = 0.f;

        #pragma unroll 4
        for (int s = 0; s < 12; s++) {
            uint32_t ah[4], b0[4], b1[4];
            LDSM4T(ah, aA  + s*(16*A_STRIDE));
            LDSM4 (b0, aB0 + s*32);
            LDSM4 (b1, aB1 + s*32);
            MMA16816(acc +  0, ah, b0[0], b0[1]);
            MMA16816(acc +  4, ah, b0[2], b0[3]);
            MMA16816(acc +  8, ah, b1[0], b1[1]);
            MMA16816(acc + 12, ah, b1[2], b1[3]);
        }

        const int tq   = (lane >> 2) & 3;
        const int mrow = lane >> 4;
        const int q2   = (lane & 3) * 2;
        #pragma unroll
        for (int j = 0; j < 4; j++) {
            #pragma unroll
            for (int i = 0; i < 2; i++) {
                int m = 4*mt + mrow + 2*i;
                if (m < NN) {
                    int o = n0 + j*8 + q2;
                    float* op = out + ((size_t)(b*NN + m)*NO + o)*NT + tt0 + tq;
                    op[0]  = fmaxf(acc[j*4 + i*2 + 0], 0.f);
                    op[NT] = fmaxf(acc[j*4 + i*2 + 1], 0.f);
                }
            }
        }
    }
}

// ---------------------------------------------------------------------------
extern "C" void kernel_launch(void* const* d_in, const int* in_sizes, int n_in,
                              void* d_out, int out_size)
{
    const float* x     = (const float*)d_in[0];   // [B,N,F_in,T]
    const float* att   = (const float*)d_in[1];   // [B,N,N]
    const float* theta = (const float*)d_in[2];   // [K,F_in,F_out]
    const float* emb   = (const float*)d_in[3];   // [N,N]
    float* out = (float*)d_out;                   // [B,N,F_out,T]

    k_prep<<<8, 512>>>(emb, theta);
    k_a2<<<NB, 1024>>>(att);

    cudaFuncSetAttribute(k_main, cudaFuncAttributeMaxDynamicSharedMemorySize,
                         DSMEM_TOTAL);
    dim3 grid(NT/TT, NB);
    k_main<<<grid, 384, DSMEM_TOTAL>>>(x, out);
}

// round 17
// speedup vs baseline: 1.7564x; 1.1859x over previous
#include <cuda_runtime.h>
#include <cuda_fp16.h>
#include <cstdint>

#define NB 64
#define NN 22
#define NF 64
#define NO 64
#define NT 512
#define TT 8              // t-tile width per CTA
#define KF 192            // combined (k,f) contraction dim

typedef unsigned long long u64;

__device__ float d_S[2*NN*NN];      // Chebyshev supports S1, S2
__device__ __half d_thT[NO*KF];     // theta^T fp16 [o][kf]
__device__ float d_a2all[NB*1080];  // per batch: 48 rows x 22 coeff + 22 diag

// ---------------------------------------------------------------------------
__device__ __forceinline__ uint32_t smem_u32(const void* p) {
    uint32_t a;
    asm("{ .reg .u64 t; cvta.to.shared.u64 t, %1; cvt.u32.u64 %0, t; }"
        : "=r"(a) : "l"(p));
    return a;
}
__device__ __forceinline__ void cp_async16(uint32_t dst, const void* src) {
    asm volatile("cp.async.ca.shared.global [%0], [%1], 16;"
                 :: "r"(dst), "l"(src) : "memory");
}
#define CP_COMMIT() asm volatile("cp.async.commit_group;" ::: "memory")
#define CP_WAIT1()  asm volatile("cp.async.wait_group 1;" ::: "memory")
#define CP_WAIT0()  asm volatile("cp.async.wait_group 0;" ::: "memory")

// ---------------------------------------------------------------------------
// warp-mma building blocks
// ---------------------------------------------------------------------------
#define LDSM4T(R, ADDR) \
    asm volatile("ldmatrix.sync.aligned.m8n8.x4.trans.shared.b16 {%0,%1,%2,%3}, [%4];" \
        : "=r"((R)[0]), "=r"((R)[1]), "=r"((R)[2]), "=r"((R)[3]) : "r"(ADDR))

#define LDSM4(R, ADDR) \
    asm volatile("ldmatrix.sync.aligned.m8n8.x4.shared.b16 {%0,%1,%2,%3}, [%4];" \
        : "=r"((R)[0]), "=r"((R)[1]), "=r"((R)[2]), "=r"((R)[3]) : "r"(ADDR))

#define MMA16816(D, A, B0, B1) \
    asm volatile("mma.sync.aligned.m16n8k16.row.col.f32.f16.f16.f32 " \
        "{%0,%1,%2,%3}, {%4,%5,%6,%7}, {%8,%9}, {%0,%1,%2,%3};" \
        : "+f"((D)[0]), "+f"((D)[1]), "+f"((D)[2]), "+f"((D)[3]) \
        : "r"((A)[0]), "r"((A)[1]), "r"((A)[2]), "r"((A)[3]), "r"(B0), "r"(B1))

// SMEM geometry (bytes) -- all dynamic
#define A_STRIDE 400      // A[kf][mt]: 192 fp16 (mt = m*8+t, pad to 192) + 16
#define B_STRIDE 400      // B[o][kf]:  192 fp16 + 16 pad
#define OFF_B    76800                        // after A (192*400)
#define OFF_A2   102400                       // after B (64*400)
#define OFF_DIAG (OFF_A2 + 1056*4)            // diag floats
#define RING_OFF (OFF_A2 + 1088*4)            // ring, 2 slots x 2048 B
#define DSMEM_TOTAL (RING_OFF + 2*2048)       // 110848 (x2 = 221696, fits)

// ---------------------------------------------------------------------------
// K_prep: supports (block 0) + theta^T fp16 (8 blocks, strided)
// ---------------------------------------------------------------------------
__global__ void k_prep(const float* __restrict__ E, const float* __restrict__ theta) {
    __shared__ float Es[NN*NN];
    __shared__ float P[NN*NN];
    __shared__ float sup[NN*NN];
    int t = threadIdx.x;
    for (int i = blockIdx.x*512 + t; i < NO*KF; i += 8*512) {
        int o = i / KF, kf = i % KF;
        d_thT[i] = __float2half(theta[kf*NO + o]);
    }
    if (blockIdx.x != 0) return;
    if (t < NN*NN) Es[t] = E[t];
    __syncthreads();
    if (t < NN*NN) {
        int i = t / NN, j = t % NN;
        float s = 0.f;
        #pragma unroll
        for (int l = 0; l < NN; l++) s += Es[i*NN + l] * Es[j*NN + l];
        P[t] = fmaxf(s, 0.f);
    }
    __syncthreads();
    if (t < NN) {
        float mx = -1e30f;
        #pragma unroll
        for (int j = 0; j < NN; j++) mx = fmaxf(mx, P[t*NN + j]);
        float den = 0.f;
        #pragma unroll
        for (int j = 0; j < NN; j++) { float e = expf(P[t*NN + j] - mx); sup[t*NN + j] = e; den += e; }
        float inv = 1.f / den;
        #pragma unroll
        for (int j = 0; j < NN; j++) sup[t*NN + j] *= inv;
    }
    __syncthreads();
    if (t < NN*NN) {
        int i = t / NN, j = t % NN;
        float eye = (i == j) ? 1.f : 0.f;
        d_S[t] = sup[t];                       // S1
        float s = 0.f;
        #pragma unroll
        for (int l = 0; l < NN; l++) s += sup[i*NN + l] * sup[l*NN + j];
        d_S[NN*NN + t] = 2.f * s - eye;        // S2
    }
}

// ---------------------------------------------------------------------------
// K_a2: per-batch coefficients (layout: 48 rows x 22 + 22 diag + pad = 1080)
// ---------------------------------------------------------------------------
__global__ void k_a2(const float* __restrict__ att) {
    int b = blockIdx.x;
    for (int t = threadIdx.x; t < 1080; t += 1024) {
        float v = 0.f;
        if (t < 968) {                     // 44 real rows x 22 n
            int row = t / 22, n = t % 22;
            int kk = row / 22, m = row % 22;
            v = d_S[kk*NN*NN + n*NN + m] * att[(b*NN + n)*NN + m];
        } else if (t >= 1056 && t < 1078) {
            int m = t - 1056;
            v = att[(b*NN + m)*NN + m];
        }
        d_a2all[b*1080 + t] = v;
    }
}

// ---------------------------------------------------------------------------
// Fused main kernel. One CTA per (b, 8-wide t-tile). 384 threads, occ 2.
// Phase 1: two t-half passes; 6 row-groups x 64 f; 8 rows x 4 t in regs;
//          a2 SMEM broadcasts; x via 2-slot cp.async ring (2 KB half-chunks).
// Phase 2: 12 warps = (mt-pair, n-half); m32 x n32 tile; B frags reused.
// ---------------------------------------------------------------------------
__global__ void __launch_bounds__(384, 2) k_main(
    const float* __restrict__ x,
    float* __restrict__ out)
{
    extern __shared__ char dsm[];

    const int tid = threadIdx.x;
    const int b   = blockIdx.y;
    const int tt0 = blockIdx.x * TT;
    const uint32_t sbase = smem_u32(dsm);
    const float*   ringf = (const float*)(dsm + RING_OFF);
    const float*   a2s   = (const float*)(dsm + OFF_A2);
    const float*   diags = (const float*)(dsm + OFF_DIAG);
    const float*   xb    = x + (size_t)b*NN*NF*NT + tt0;

    // ---- prologue: stage B (1536 lines) + a2 (270 lines) via cp.async ----
    #pragma unroll
    for (int j = 0; j < 5; j++) {
        int L = tid + j*384;
        if (L < 1536) {
            int o = L / 24, ch = L % 24;
            cp_async16(sbase + OFF_B + o*B_STRIDE + ch*16, d_thT + o*KF + ch*8);
        } else if (L < 1536 + 270) {
            int q = L - 1536;
            cp_async16(sbase + OFF_A2 + q*16, d_a2all + b*1080 + q*4);
        }
    }
    CP_COMMIT();                                  // group BA (all threads)

    // zero-fill A pad cols (mt 176..191, bytes 352..383)
    if (tid < 192) {
        uint32_t zb = sbase + tid*A_STRIDE + 352;
        asm volatile("st.shared.b64 [%0], %1;" :: "r"(zb),     "l"(0ULL));
        asm volatile("st.shared.b64 [%0], %1;" :: "r"(zb + 8), "l"(0ULL));
    }

    // x ring: half-chunk c = n rows {2c,2c+1} x 4 t, 2048 B, slot c&1,
    // 128 issuer threads, one 16B line per (n,f).
    const int cn2 = tid >> 6;          // 0..1 (valid tid<128)
    const int cf  = tid & 63;
    const uint32_t cdst0 = sbase + RING_OFF + (uint32_t)((cn2 << 10) | (cf << 4));

    const int G = tid >> 6;            // 0..5, warp-uniform
    const int f = tid & 63;
    const int r0 = G * 8;              // rows r0..r0+7 (44..47 zero coeff)

    // ---- phase 1: two passes over t-halves ----
    #pragma unroll
    for (int p = 0; p < 2; p++) {
        const float* csrcp = xb + ((size_t)cn2*NF + cf)*NT + p*4;

        if (tid < 128) {
            cp_async16(cdst0,        csrcp);            CP_COMMIT();  // c0
            cp_async16(cdst0 + 2048, csrcp + 2*NF*NT);  CP_COMMIT();  // c1
        }

        float a[8][4];
        #pragma unroll
        for (int i = 0; i < 8; i++)
            #pragma unroll
            for (int t = 0; t < 4; t++) a[i][t] = 0.f;

        #pragma unroll
        for (int c = 0; c < 11; c++) {
            if (tid < 128) { if (c < 10) CP_WAIT1(); else CP_WAIT0(); }
            else if (p == 0 && c == 0) { CP_WAIT0(); }      // a2/B ready
            __syncthreads();
            const float* xp = ringf + ((c & 1) << 9);
            float4 xv0 = ((const float4*)xp)[f];            // n = 2c
            float4 xv1 = ((const float4*)(xp + 256))[f];    // n = 2c+1
            __syncthreads();                 // slot c&1 reusable
            if (tid < 128 && c < 9) {
                cp_async16(cdst0 + (uint32_t)(((c+2) & 1) << 11),
                           csrcp + (size_t)(2*(c+2))*NF*NT);
                CP_COMMIT();
            }
            #pragma unroll
            for (int i = 0; i < 8; i++) {
                float2 aa = *(const float2*)(a2s + (r0 + i)*22 + 2*c);
                a[i][0] = fmaf(aa.x, xv0.x, a[i][0]);
                a[i][1] = fmaf(aa.x, xv0.y, a[i][1]);
                a[i][2] = fmaf(aa.x, xv0.z, a[i][2]);
                a[i][3] = fmaf(aa.x, xv0.w, a[i][3]);
                a[i][0] = fmaf(aa.y, xv1.x, a[i][0]);
                a[i][1] = fmaf(aa.y, xv1.y, a[i][1]);
                a[i][2] = fmaf(aa.y, xv1.z, a[i][2]);
                a[i][3] = fmaf(aa.y, xv1.w, a[i][3]);
            }
            if (G == 5) {
                // diag (k=0) plane: A row = f, cols (m*8 + p*4)
                float d0 = diags[2*c], d1 = diags[2*c + 1];
                __half2 h0 = __floats2half2_rn(d0*xv0.x, d0*xv0.y);
                __half2 h1 = __floats2half2_rn(d0*xv0.z, d0*xv0.w);
                __half2 h2 = __floats2half2_rn(d1*xv1.x, d1*xv1.y);
                __half2 h3 = __floats2half2_rn(d1*xv1.z, d1*xv1.w);
                uint32_t base = sbase + f*A_STRIDE + p*8;
                u64 p0 = ((u64)*(uint32_t*)&h1 << 32) | *(uint32_t*)&h0;
                u64 p1 = ((u64)*(uint32_t*)&h3 << 32) | *(uint32_t*)&h2;
                asm volatile("st.shared.b64 [%0], %1;" :: "r"(base + (2*c)*16),   "l"(p0));
                asm volatile("st.shared.b64 [%0], %1;" :: "r"(base + (2*c+1)*16), "l"(p1));
            }
        }
        // store heavy rows for this t-half
        #pragma unroll
        for (int i = 0; i < 8; i++) {
            int row = r0 + i;
            if (row < 44) {
                int kk = row / 22, m = row - kk*22;
                __half2 h0 = __floats2half2_rn(a[i][0], a[i][1]);
                __half2 h1 = __floats2half2_rn(a[i][2], a[i][3]);
                u64 pk = ((u64)*(uint32_t*)&h1 << 32) | *(uint32_t*)&h0;
                asm volatile("st.shared.b64 [%0], %1;"
                    :: "r"(sbase + ((1 + kk)*64 + f)*A_STRIDE + m*16 + p*8), "l"(pk));
            }
        }
    }
    __syncthreads();

    // ---- phase 2: 12 warps = (mt-pair 0..5, n-half); m32 x n32 tiles ----
    {
        const int w    = tid >> 5;
        const int lane = tid & 31;
        const int mtp = w >> 1;             // 0..5 (mt tiles 2*mtp, 2*mtp+1)
        const int nh  = w & 1;
        const int n0  = nh * 32;

        const int lrow = (lane & 7) + ((lane >> 4) << 3);
        const int lga  = ((lane >> 3) & 1) * 8;
        uint32_t aA = sbase + lrow*A_STRIDE + (mtp*32 + lga)*2;

        const int borow = ((lane >> 4) << 3) + (lane & 7);
        uint32_t aB0 = sbase + OFF_B + (n0 + borow)*B_STRIDE + ((lane >> 3) & 1)*16;
        uint32_t aB1 = aB0 + 16*B_STRIDE;

        float acc[32];
        #pragma unroll
        for (int i = 0; i < 32; i++) acc[i] = 0.f;

        #pragma unroll 4
        for (int s = 0; s < 12; s++) {
            uint32_t ah0[4], ah1[4], b0[4], b1[4];
            LDSM4T(ah0, aA + s*(16*A_STRIDE));
            LDSM4T(ah1, aA + s*(16*A_STRIDE) + 32);
            LDSM4 (b0, aB0 + s*32);
            LDSM4 (b1, aB1 + s*32);
            MMA16816(acc +  0, ah0, b0[0], b0[1]);
            MMA16816(acc +  4, ah0, b0[2], b0[3]);
            MMA16816(acc +  8, ah0, b1[0], b1[1]);
            MMA16816(acc + 12, ah0, b1[2], b1[3]);
            MMA16816(acc + 16, ah1, b0[0], b0[1]);
            MMA16816(acc + 20, ah1, b0[2], b0[3]);
            MMA16816(acc + 24, ah1, b1[0], b1[1]);
            MMA16816(acc + 28, ah1, b1[2], b1[3]);
        }

        // epilogue: tile T = 2*mtp + h covers mt rows T*16..+15; mt = m*8 + t
        // frag row r = lane/4 + 8i -> m = 2T + i, t = lane>>2
        const int tq = lane >> 2;           // 0..7
        const int q2 = (lane & 3) * 2;
        #pragma unroll
        for (int h = 0; h < 2; h++) {
            #pragma unroll
            for (int j = 0; j < 4; j++) {
                #pragma unroll
                for (int i = 0; i < 2; i++) {
                    int m = 4*mtp + 2*h + i;
                    if (m < NN) {
                        int o = n0 + j*8 + q2;
                        float* op = out + ((size_t)(b*NN + m)*NO + o)*NT + tt0 + tq;
                        op[0]  = fmaxf(acc[h*16 + j*4 + i*2 + 0], 0.f);
                        op[NT] = fmaxf(acc[h*16 + j*4 + i*2 + 1], 0.f);
                    }
                }
            }
        }
    }
}

// ---------------------------------------------------------------------------
extern "C" void kernel_launch(void* const* d_in, const int* in_sizes, int n_in,
                              void* d_out, int out_size)
{
    const float* x     = (const float*)d_in[0];   // [B,N,F_in,T]
    const float* att   = (const float*)d_in[1];   // [B,N,N]
    const float* theta = (const float*)d_in[2];   // [K,F_in,F_out]
    const float* emb   = (const float*)d_in[3];   // [N,N]
    float* out = (float*)d_out;                   // [B,N,F_out,T]

    k_prep<<<8, 512>>>(emb, theta);
    k_a2<<<NB, 1024>>>(att);

    cudaFuncSetAttribute(k_main, cudaFuncAttributeMaxDynamicSharedMemorySize,
                         DSMEM_TOTAL);
    dim3 grid(NT/TT, NB);
    k_main<<<grid, 384, DSMEM_TOTAL>>>(x, out);
}